// round 1
// baseline (speedup 1.0000x reference)
#include <cuda_runtime.h>
#include <cstdint>

#define BB 8
#define NN 1024
#define DIN 64
#define HH 128
#define MSGD 128
#define LL 5
#define TGT 12
#define NLAYERS 3
#define ROWS (BB*NN)   // 8192

// ---------------- scratch (no allocations allowed) ----------------
__device__ float g_h   [ROWS*HH];          // current hidden state
__device__ float g_h0  [ROWS*HH];          // padded input features
__device__ float g_Ml  [ROWS*LL*MSGD];     // per-label candidate messages [row][l][o]
__device__ float g_agg [ROWS*MSGD];        // aggregated messages
__device__ float g_aggP[4][ROWS*MSGD];     // w-split partials
__device__ float g_gi  [ROWS*3*HH];        // GRU input gates
__device__ float g_gh  [ROWS*3*HH];        // GRU hidden gates
__device__ float g_maskN[ROWS];            // node mask (sum|h_in|>0)
__device__ float g_maskR[ROWS];            // read mask (sum h0 > 0)

// ---------------- init: pad h_in -> h0, h; compute masks ----------------
__global__ void k_init(const float* __restrict__ h_in)
{
    int n = blockIdx.x;
    int t = threadIdx.x;    // 128
    float v = (t < DIN) ? h_in[n*DIN + t] : 0.f;
    g_h0[n*HH + t] = v;
    g_h [n*HH + t] = v;
    __shared__ float sa[128], ss[128];
    sa[t] = fabsf(v);
    ss[t] = v;
    __syncthreads();
    for (int s = 64; s > 0; s >>= 1) {
        if (t < s) { sa[t] += sa[t+s]; ss[t] += ss[t+s]; }
        __syncthreads();
    }
    if (t == 0) {
        g_maskN[n] = (sa[0] > 0.f) ? 1.f : 0.f;
        g_maskR[n] = (ss[0] > 0.f) ? 1.f : 0.f;
    }
}

__global__ void k_zero(float* __restrict__ out)
{
    int i = threadIdx.x;
    if (i < BB*TGT) out[i] = 0.f;
}

// ---------------- generic tiled SGEMM: C[row, y*128+c] = X[row,:]@Wp + bias ----------------
// X: [R,128] row-major. Wp = W + blockIdx.y*wBlkStride, inner k-stride ldW.
// 64x128 tile per block, 256 threads, 4x8 micro-tile.
__global__ void __launch_bounds__(256) k_gemm(
    const float* __restrict__ X, const float* __restrict__ W,
    const float* __restrict__ bias, float* __restrict__ C,
    int ldW, int wBlkStride, int ldC)
{
    const float* Wp = W + (size_t)blockIdx.y * wBlkStride;
    int row0  = blockIdx.x << 6;
    int cBase = blockIdx.y << 7;
    __shared__ float sX[64][33];
    __shared__ float sW[32][128];
    int tid = threadIdx.x;
    int tx = tid & 15, ty = tid >> 4;

    float acc[4][8];
#pragma unroll
    for (int i = 0; i < 4; i++)
#pragma unroll
        for (int j = 0; j < 8; j++) acc[i][j] = 0.f;

    for (int k0 = 0; k0 < HH; k0 += 32) {
#pragma unroll
        for (int rep = 0; rep < 8; rep++) {
            int e2 = rep*256 + tid;
            int r = e2 >> 5, kk = e2 & 31;
            sX[r][kk] = X[(row0 + r)*HH + k0 + kk];
        }
#pragma unroll
        for (int rep = 0; rep < 16; rep++) {
            int e2 = rep*256 + tid;
            int kk = e2 >> 7, c = e2 & 127;
            sW[kk][c] = Wp[(k0 + kk)*ldW + c];
        }
        __syncthreads();
#pragma unroll
        for (int kk = 0; kk < 32; kk++) {
            float a[4];
#pragma unroll
            for (int i = 0; i < 4; i++) a[i] = sX[ty*4 + i][kk];
            float4 b0 = *(const float4*)(&sW[kk][tx*8]);
            float4 b1 = *(const float4*)(&sW[kk][tx*8 + 4]);
            float b[8] = {b0.x,b0.y,b0.z,b0.w,b1.x,b1.y,b1.z,b1.w};
#pragma unroll
            for (int i = 0; i < 4; i++)
#pragma unroll
                for (int j = 0; j < 8; j++) acc[i][j] += a[i]*b[j];
        }
        __syncthreads();
    }

#pragma unroll
    for (int i = 0; i < 4; i++) {
        int row = row0 + ty*4 + i;
        int c0 = cBase + tx*8;
        float bv[8];
#pragma unroll
        for (int j = 0; j < 8; j++) bv[j] = bias ? bias[c0 + j] : 0.f;
        float4 o0, o1;
        o0.x = acc[i][0]+bv[0]; o0.y = acc[i][1]+bv[1];
        o0.z = acc[i][2]+bv[2]; o0.w = acc[i][3]+bv[3];
        o1.x = acc[i][4]+bv[4]; o1.y = acc[i][5]+bv[5];
        o1.z = acc[i][6]+bv[6]; o1.w = acc[i][7]+bv[7];
        *(float4*)(&C[(size_t)row*ldC + c0    ]) = o0;
        *(float4*)(&C[(size_t)row*ldC + c0 + 4]) = o1;
    }
}

// ---------------- label-gather aggregation ----------------
// agg[b,v,o] = sum_w g[b,v,w] * Ml[b,w,e[b,v,w],o]
// block: (b, 64-v-tile) x w-split of 256. 256 threads: tx=o4 (0..31), vg (0..7).
__global__ void __launch_bounds__(256) k_agg(
    const float* __restrict__ g, const int* __restrict__ e)
{
    int b  = blockIdx.x >> 4;
    int v0 = (blockIdx.x & 15) << 6;
    int sp = blockIdx.y;          // 0..3
    int wBeg = sp << 8;           // 256 w's per split
    int tid = threadIdx.x;
    int tx = tid & 31;            // float4 index over o
    int vg = tid >> 5;            // 0..7

    __shared__ float4 sM[8][LL][32];   // [w][label][o4]
    __shared__ float  sG[64][8];
    __shared__ int    sE[64][8];

    float4 acc[8];
#pragma unroll
    for (int i = 0; i < 8; i++) acc[i] = make_float4(0.f,0.f,0.f,0.f);

    const float4* Ml4 = (const float4*)g_Ml;

    for (int w0 = wBeg; w0 < wBeg + 256; w0 += 8) {
        // stage Ml rows: 8 w x 5 labels x 32 float4 = 1280 float4
#pragma unroll
        for (int rep = 0; rep < 5; rep++) {
            int idx = rep*256 + tid;
            int w  = idx / 160;
            int r  = idx - w*160;
            int l  = r >> 5;
            int o4 = r & 31;
            sM[w][l][o4] = Ml4[((size_t)((b*NN + w0 + w)*LL + l))*32 + o4];
        }
        // stage g and e tiles: 64 v x 8 w
#pragma unroll
        for (int rep = 0; rep < 2; rep++) {
            int idx = rep*256 + tid;
            int v = idx >> 3, w = idx & 7;
            size_t gidx = (size_t)(b*NN + v0 + v)*NN + w0 + w;
            sG[v][w] = g[gidx];
            sE[v][w] = e[gidx];
        }
        __syncthreads();

#pragma unroll
        for (int i = 0; i < 8; i++) {
            int v = vg*8 + i;
#pragma unroll
            for (int w = 0; w < 8; w++) {
                float gv  = sG[v][w];
                int   lab = sE[v][w];
                float4 m = sM[w][lab][tx];
                acc[i].x += gv*m.x; acc[i].y += gv*m.y;
                acc[i].z += gv*m.z; acc[i].w += gv*m.w;
            }
        }
        __syncthreads();
    }

    float4* outP = (float4*)g_aggP[sp];
#pragma unroll
    for (int i = 0; i < 8; i++) {
        int v = v0 + vg*8 + i;
        outP[(size_t)(b*NN + v)*32 + tx] = acc[i];
    }
}

__global__ void k_aggsum()
{
    int i = blockIdx.x*256 + threadIdx.x;   // ROWS*MSGD/4 float4's
    const float4* p0 = (const float4*)g_aggP[0];
    const float4* p1 = (const float4*)g_aggP[1];
    const float4* p2 = (const float4*)g_aggP[2];
    const float4* p3 = (const float4*)g_aggP[3];
    float4 a = p0[i], b = p1[i], c = p2[i], d = p3[i];
    float4 s;
    s.x = (a.x+b.x) + (c.x+d.x);
    s.y = (a.y+b.y) + (c.y+d.y);
    s.z = (a.z+b.z) + (c.z+d.z);
    s.w = (a.w+b.w) + (c.w+d.w);
    ((float4*)g_agg)[i] = s;
}

// ---------------- GRU gate + mask ----------------
__global__ void k_gru()
{
    int idx = blockIdx.x*256 + threadIdx.x;   // ROWS*HH threads
    int n = idx >> 7;
    int c = idx & 127;
    int base = n*384 + c;
    float ir = g_gi[base], iz = g_gi[base+128], in_ = g_gi[base+256];
    float hr = g_gh[base], hz = g_gh[base+128], hn  = g_gh[base+256];
    float r = 1.f/(1.f + __expf(-(ir + hr)));
    float z = 1.f/(1.f + __expf(-(iz + hz)));
    float nn = tanhf(in_ + r*hn);
    float h  = g_h[idx];
    g_h[idx] = ((1.f - z)*nn + z*h) * g_maskN[n];
}

// ---------------- readout ----------------
__global__ void k_readout(const float* __restrict__ Wg, const float* __restrict__ bg,
                          const float* __restrict__ Wo, const float* __restrict__ bo,
                          float* __restrict__ out)
{
    int n = blockIdx.x;
    int t = threadIdx.x;   // 128
    float hT = g_h [n*HH + t];
    float h0 = g_h0[n*HH + t];
    __shared__ float red[24][128];
    __shared__ float s2[24];
#pragma unroll
    for (int j = 0; j < TGT; j++) {
        red[j][t]      = hT*Wg[t*TGT + j] + h0*Wg[(HH + t)*TGT + j];
        red[12 + j][t] = hT*Wo[t*TGT + j];
    }
    __syncthreads();
    if (t < 24) {
        float s = 0.f;
        for (int i = 0; i < 128; i++) s += red[t][i];
        s2[t] = s;
    }
    __syncthreads();
    if (t < TGT) {
        float gate = 1.f/(1.f + __expf(-(s2[t] + bg[t])));
        float val  = gate*(s2[12 + t] + bo[t]) * g_maskR[n];
        atomicAdd(&out[(n >> 10)*TGT + t], val);
    }
}

// ---------------- launch ----------------
extern "C" void kernel_launch(void* const* d_in, const int* in_sizes, int n_in,
                              void* d_out, int out_size)
{
    const float* g    = (const float*)d_in[0];
    const float* h_in = (const float*)d_in[1];
    const int*   e    = (const int*)  d_in[2];
    const float* A    = (const float*)d_in[3];
    const float* Wi   = (const float*)d_in[4];
    const float* Wh   = (const float*)d_in[5];
    const float* bi   = (const float*)d_in[6];
    const float* bh   = (const float*)d_in[7];
    const float* Wg   = (const float*)d_in[8];
    const float* bg   = (const float*)d_in[9];
    const float* Wo   = (const float*)d_in[10];
    const float* bo   = (const float*)d_in[11];
    float* out = (float*)d_out;

    float *p_h, *p_Ml, *p_agg, *p_gi, *p_gh;
    cudaGetSymbolAddress((void**)&p_h,   g_h);
    cudaGetSymbolAddress((void**)&p_Ml,  g_Ml);
    cudaGetSymbolAddress((void**)&p_agg, g_agg);
    cudaGetSymbolAddress((void**)&p_gi,  g_gi);
    cudaGetSymbolAddress((void**)&p_gh,  g_gh);

    k_init<<<ROWS, 128>>>(h_in);
    k_zero<<<1, 128>>>(out);

    for (int layer = 0; layer < NLAYERS; layer++) {
        // Ml[row, l, :] = h[row,:] @ A[l]
        k_gemm<<<dim3(ROWS/64, LL), 256>>>(p_h, A, nullptr, p_Ml,
                                           MSGD, HH*MSGD, LL*MSGD);
        // label-gather aggregation (w-split x4) + reduce
        k_agg<<<dim3(BB*(NN/64), 4), 256>>>(g, e);
        k_aggsum<<<ROWS*MSGD/4/256, 256>>>();
        // GRU gate pre-activations
        k_gemm<<<dim3(ROWS/64, 3), 256>>>(p_agg, Wi, bi, p_gi, 3*HH, HH, 3*HH);
        k_gemm<<<dim3(ROWS/64, 3), 256>>>(p_h,   Wh, bh, p_gh, 3*HH, HH, 3*HH);
        k_gru<<<ROWS*HH/256, 256>>>();
    }

    k_readout<<<ROWS, 128>>>(Wg, bg, Wo, bo, out);
}

// round 4
// speedup vs baseline: 1.1502x; 1.1502x over previous
#include <cuda_runtime.h>
#include <cstdint>

#define BB 8
#define NN 1024
#define DIN 64
#define HH 128
#define MSGD 128
#define LL 5
#define TGT 12
#define NLAYERS 3
#define ROWS (BB*NN)   // 8192

// ================= scratch =================
__device__ float g_h   [ROWS*HH];
__device__ float g_h0  [ROWS*HH];
__device__ float g_Ml  [ROWS*LL*MSGD];     // [row][l*128+o], exact fp32
__device__ float g_aggP[4][ROWS*MSGD];     // 4-way w-split partials
__device__ float g_gi  [ROWS*3*HH];
__device__ float g_gh  [ROWS*3*HH];
__device__ float g_maskN[ROWS];
__device__ float g_maskR[ROWS];

// ================= helpers =================
__device__ __forceinline__ uint32_t f2tf(float f){
    uint32_t u; asm("cvt.rna.tf32.f32 %0, %1;" : "=r"(u) : "f"(f)); return u;
}
__device__ __forceinline__ void mma_tf32(float* d, const uint32_t* a, const uint32_t* b){
    asm volatile("mma.sync.aligned.m16n8k8.row.col.f32.tf32.tf32.f32 "
        "{%0,%1,%2,%3}, {%4,%5,%6,%7}, {%8,%9}, {%0,%1,%2,%3};"
        : "+f"(d[0]), "+f"(d[1]), "+f"(d[2]), "+f"(d[3])
        : "r"(a[0]), "r"(a[1]), "r"(a[2]), "r"(a[3]), "r"(b[0]), "r"(b[1]));
}

// ================= init =================
__global__ void k_init(const float* __restrict__ h_in)
{
    int n = blockIdx.x;
    int t = threadIdx.x;
    float v = (t < DIN) ? h_in[n*DIN + t] : 0.f;
    g_h0[n*HH + t] = v;
    g_h [n*HH + t] = v;
    __shared__ float sa[128], ss[128];
    sa[t] = fabsf(v); ss[t] = v;
    __syncthreads();
    for (int s = 64; s > 0; s >>= 1) {
        if (t < s) { sa[t] += sa[t+s]; ss[t] += ss[t+s]; }
        __syncthreads();
    }
    if (t == 0) {
        g_maskN[n] = (sa[0] > 0.f) ? 1.f : 0.f;
        g_maskR[n] = (ss[0] > 0.f) ? 1.f : 0.f;
    }
}

__global__ void k_zero(float* __restrict__ out)
{
    int i = threadIdx.x;
    if (i < BB*TGT) out[i] = 0.f;
}

// ================= tf32x3 split GEMM =================
// C[128-rowtile, 128-coltile] = (sum of NSUM X's) @ Wp + bias, fp32-accurate.
// X,W split on-the-fly into tf32 hi/lo; acc = Xh@Wh + Xh@Wl + Xl@Wh.
// 256 thr = 8 warps, warp = 32v x 64o. smem: Xh/Xl [128][36], Wh/Wl [32][136].
#define GEMM_SMEM ((2*4608 + 2*4352)*4)   // 71680 B

template<int NSUM>
__global__ void __launch_bounds__(256) k_gemm3(
    const float* __restrict__ X0, const float* __restrict__ X1,
    const float* __restrict__ X2, const float* __restrict__ X3,
    const float* __restrict__ W, const float* __restrict__ bias,
    float* __restrict__ C, int ldW, int wBlk, int ldC)
{
    extern __shared__ float smf[];
    float* sXh = smf;
    float* sXl = smf + 4608;
    float* sWh = smf + 2*4608;
    float* sWl = smf + 2*4608 + 4352;
    const int tid = threadIdx.x, lane = tid & 31, wid = tid >> 5;
    const int tq = lane & 3, gid = lane >> 2;
    const int row0  = blockIdx.x << 7;
    const int cBase = blockIdx.y << 7;
    const float* Wp = W + (size_t)blockIdx.y * wBlk;
    const int vbase = (wid >> 1) << 5;
    const int obase = (wid & 1) << 6;

    float acc[2][8][4];
#pragma unroll
    for (int i = 0; i < 2; i++)
#pragma unroll
        for (int j = 0; j < 8; j++)
#pragma unroll
            for (int k = 0; k < 4; k++) acc[i][j][k] = 0.f;

    float4 xp[4], wpr[4];

    auto ldg = [&](int ch) {
        int k0 = ch << 5;
#pragma unroll
        for (int r = 0; r < 4; r++) {
            int idx = (r << 8) + tid; int v = idx >> 3, k4 = idx & 7;
            size_t off = (size_t)(row0 + v)*128 + k0 + (k4 << 2);
            xp[r] = *(const float4*)(X0 + off);
            if (NSUM >= 2) {
                float4 t = *(const float4*)(X1 + off);
                xp[r].x += t.x; xp[r].y += t.y; xp[r].z += t.z; xp[r].w += t.w;
            }
            if (NSUM >= 3) {
                float4 t = *(const float4*)(X2 + off);
                xp[r].x += t.x; xp[r].y += t.y; xp[r].z += t.z; xp[r].w += t.w;
            }
            if (NSUM >= 4) {
                float4 t = *(const float4*)(X3 + off);
                xp[r].x += t.x; xp[r].y += t.y; xp[r].z += t.z; xp[r].w += t.w;
            }
        }
#pragma unroll
        for (int r = 0; r < 4; r++) {
            int idx = (r << 8) + tid; int k = idx >> 5, o4 = idx & 31;
            wpr[r] = *(const float4*)(Wp + (size_t)(k0 + k)*ldW + (o4 << 2));
        }
    };

    ldg(0);
    for (int ch = 0; ch < 4; ch++) {
        // split + STS
#pragma unroll
        for (int r = 0; r < 4; r++) {
            int idx = (r << 8) + tid; int v = idx >> 3, k4 = idx & 7;
            uint4 h4, l4;
            h4.x = f2tf(xp[r].x); l4.x = f2tf(xp[r].x - __uint_as_float(h4.x));
            h4.y = f2tf(xp[r].y); l4.y = f2tf(xp[r].y - __uint_as_float(h4.y));
            h4.z = f2tf(xp[r].z); l4.z = f2tf(xp[r].z - __uint_as_float(h4.z));
            h4.w = f2tf(xp[r].w); l4.w = f2tf(xp[r].w - __uint_as_float(h4.w));
            *(uint4*)&sXh[v*36 + (k4 << 2)] = h4;
            *(uint4*)&sXl[v*36 + (k4 << 2)] = l4;
        }
#pragma unroll
        for (int r = 0; r < 4; r++) {
            int idx = (r << 8) + tid; int k = idx >> 5, o4 = idx & 31;
            uint4 h4, l4;
            h4.x = f2tf(wpr[r].x); l4.x = f2tf(wpr[r].x - __uint_as_float(h4.x));
            h4.y = f2tf(wpr[r].y); l4.y = f2tf(wpr[r].y - __uint_as_float(h4.y));
            h4.z = f2tf(wpr[r].z); l4.z = f2tf(wpr[r].z - __uint_as_float(h4.z));
            h4.w = f2tf(wpr[r].w); l4.w = f2tf(wpr[r].w - __uint_as_float(h4.w));
            *(uint4*)&sWh[k*136 + (o4 << 2)] = h4;
            *(uint4*)&sWl[k*136 + (o4 << 2)] = l4;
        }
        __syncthreads();
        if (ch < 3) ldg(ch + 1);
        const uint32_t* bXh = (const uint32_t*)sXh;
        const uint32_t* bXl = (const uint32_t*)sXl;
        const uint32_t* bWh = (const uint32_t*)sWh;
        const uint32_t* bWl = (const uint32_t*)sWl;
#pragma unroll
        for (int k8 = 0; k8 < 4; k8++) {
            uint32_t ah[2][4], al[2][4];
            int kk = (k8 << 3) + tq;
#pragma unroll
            for (int mt = 0; mt < 2; mt++) {
                int vr = vbase + (mt << 4) + gid;
                ah[mt][0] = bXh[vr*36 + kk];       ah[mt][1] = bXh[(vr+8)*36 + kk];
                ah[mt][2] = bXh[vr*36 + kk + 4];   ah[mt][3] = bXh[(vr+8)*36 + kk + 4];
                al[mt][0] = bXl[vr*36 + kk];       al[mt][1] = bXl[(vr+8)*36 + kk];
                al[mt][2] = bXl[vr*36 + kk + 4];   al[mt][3] = bXl[(vr+8)*36 + kk + 4];
            }
#pragma unroll
            for (int nt = 0; nt < 8; nt++) {
                int o = obase + (nt << 3) + gid;
                uint32_t bh2[2] = { bWh[kk*136 + o], bWh[(kk+4)*136 + o] };
                uint32_t bl2[2] = { bWl[kk*136 + o], bWl[(kk+4)*136 + o] };
                mma_tf32(acc[0][nt], ah[0], bh2);
                mma_tf32(acc[0][nt], ah[0], bl2);
                mma_tf32(acc[0][nt], al[0], bh2);
                mma_tf32(acc[1][nt], ah[1], bh2);
                mma_tf32(acc[1][nt], ah[1], bl2);
                mma_tf32(acc[1][nt], al[1], bh2);
            }
        }
        __syncthreads();
    }

#pragma unroll
    for (int mt = 0; mt < 2; mt++)
#pragma unroll
        for (int nt = 0; nt < 8; nt++) {
            int row = row0 + vbase + (mt << 4) + gid;
            int col = cBase + obase + (nt << 3) + (tq << 1);
            float b0 = 0.f, b1 = 0.f;
            if (bias) { b0 = bias[col]; b1 = bias[col + 1]; }
            *(float2*)&C[(size_t)row*ldC + col] =
                make_float2(acc[mt][nt][0] + b0, acc[mt][nt][1] + b1);
            *(float2*)&C[(size_t)(row + 8)*ldC + col] =
                make_float2(acc[mt][nt][2] + b0, acc[mt][nt][3] + b1);
        }
}

// ================= exact fp32 gather aggregation =================
// aggP[ws][b,v,o] = sum_{w in ws-split} g[b,v,w] * Ml[b,w,e[b,v,w]][o]
// grid: (8b*16vt, 4ws). 256 thr = 8 warps; warp: lanes = o (float4), 8 v's.
__global__ void __launch_bounds__(256, 4) k_agg(
    const float* __restrict__ g, const int* __restrict__ e)
{
    __shared__ float4 sM[8][LL][32];     // 20 KB: [w][label][o4]
    __shared__ float2 sGE[64][8];        // 4 KB: (g, e-as-float)

    const int tid = threadIdx.x, lane = tid & 31, wid = tid >> 5;
    const int b  = blockIdx.x >> 4;
    const int v0 = (blockIdx.x & 15) << 6;
    const int wbeg = blockIdx.y << 8;    // 256 w per split

    float4 acc[8];
#pragma unroll
    for (int i = 0; i < 8; i++) acc[i] = make_float4(0.f, 0.f, 0.f, 0.f);

    for (int c = 0; c < 32; c++) {
        int w0 = wbeg + (c << 3);
        // stage Ml rows (flat copy: 8 w-rows x 640 floats = 1280 float4)
        {
            const float4* src = (const float4*)(g_Ml + (size_t)((b << 10) + w0)*640);
            float4* dstM = &sM[0][0][0];
#pragma unroll
            for (int r = 0; r < 5; r++) dstM[r*256 + tid] = src[r*256 + tid];
        }
        // stage g/e (v = tid>>2, two w-pairs each)
        {
            int v = tid >> 2, wp = tid & 3;
            size_t off = ((size_t)((b << 10) + v0 + v) << 10) + w0 + (wp << 1);
            float2 gg = *(const float2*)(g + off);
            int2   ee = *(const int2*)(e + off);
            sGE[v][(wp << 1)    ] = make_float2(gg.x, __int_as_float(ee.x));
            sGE[v][(wp << 1) + 1] = make_float2(gg.y, __int_as_float(ee.y));
        }
        __syncthreads();
#pragma unroll
        for (int i = 0; i < 8; i++) {
            int v = (wid << 3) + i;
#pragma unroll
            for (int w = 0; w < 8; w++) {
                float2 ge = sGE[v][w];
                int lab = __float_as_int(ge.y);
                float4 m = sM[w][lab][lane];
                acc[i].x += ge.x * m.x; acc[i].y += ge.x * m.y;
                acc[i].z += ge.x * m.z; acc[i].w += ge.x * m.w;
            }
        }
        __syncthreads();
    }

    float* dst = g_aggP[blockIdx.y];
#pragma unroll
    for (int i = 0; i < 8; i++) {
        int row = (b << 10) + v0 + (wid << 3) + i;
        *(float4*)&dst[(size_t)row*128 + (lane << 2)] = acc[i];
    }
}

// ================= GRU =================
__global__ void k_gru()
{
    int idx = blockIdx.x*256 + threadIdx.x;
    int n = idx >> 7;
    int c = idx & 127;
    int base = n*384 + c;
    float ir = g_gi[base], iz = g_gi[base+128], in_ = g_gi[base+256];
    float hr = g_gh[base], hz = g_gh[base+128], hn  = g_gh[base+256];
    float r = 1.f/(1.f + __expf(-(ir + hr)));
    float z = 1.f/(1.f + __expf(-(iz + hz)));
    float nn = tanhf(in_ + r*hn);
    float h  = g_h[idx];
    g_h[idx] = ((1.f - z)*nn + z*h) * g_maskN[n];
}

// ================= readout =================
__global__ void k_readout(const float* __restrict__ Wg, const float* __restrict__ bg,
                          const float* __restrict__ Wo, const float* __restrict__ bo,
                          float* __restrict__ out)
{
    int n = blockIdx.x;
    int t = threadIdx.x;
    float hT = g_h [n*HH + t];
    float h0 = g_h0[n*HH + t];
    __shared__ float red[24][128];
    __shared__ float s2[24];
#pragma unroll
    for (int j = 0; j < TGT; j++) {
        red[j][t]      = hT*Wg[t*TGT + j] + h0*Wg[(HH + t)*TGT + j];
        red[12 + j][t] = hT*Wo[t*TGT + j];
    }
    __syncthreads();
    if (t < 24) {
        float s = 0.f;
        for (int i = 0; i < 128; i++) s += red[t][i];
        s2[t] = s;
    }
    __syncthreads();
    if (t < TGT) {
        float gate = 1.f/(1.f + __expf(-(s2[t] + bg[t])));
        float val  = gate*(s2[12 + t] + bo[t]) * g_maskR[n];
        atomicAdd(&out[(n >> 10)*TGT + t], val);
    }
}

// ================= launch =================
extern "C" void kernel_launch(void* const* d_in, const int* in_sizes, int n_in,
                              void* d_out, int out_size)
{
    const float* g    = (const float*)d_in[0];
    const float* h_in = (const float*)d_in[1];
    const int*   e    = (const int*)  d_in[2];
    const float* A    = (const float*)d_in[3];
    const float* Wi   = (const float*)d_in[4];
    const float* Wh   = (const float*)d_in[5];
    const float* bi   = (const float*)d_in[6];
    const float* bh   = (const float*)d_in[7];
    const float* Wg   = (const float*)d_in[8];
    const float* bg   = (const float*)d_in[9];
    const float* Wo   = (const float*)d_in[10];
    const float* bo   = (const float*)d_in[11];
    float* out = (float*)d_out;

    static int attr_set = 0;
    if (!attr_set) {
        cudaFuncSetAttribute(k_gemm3<1>, cudaFuncAttributeMaxDynamicSharedMemorySize, GEMM_SMEM);
        cudaFuncSetAttribute(k_gemm3<4>, cudaFuncAttributeMaxDynamicSharedMemorySize, GEMM_SMEM);
        attr_set = 1;
    }

    float *p_h, *p_Ml, *p_P0, *p_gi, *p_gh;
    cudaGetSymbolAddress((void**)&p_h,  g_h);
    cudaGetSymbolAddress((void**)&p_Ml, g_Ml);
    cudaGetSymbolAddress((void**)&p_P0, g_aggP);
    cudaGetSymbolAddress((void**)&p_gi, g_gi);
    cudaGetSymbolAddress((void**)&p_gh, g_gh);
    float* p_P1 = p_P0 + ROWS*MSGD;
    float* p_P2 = p_P0 + 2*ROWS*MSGD;
    float* p_P3 = p_P0 + 3*ROWS*MSGD;

    k_init<<<ROWS, 128>>>(h_in);
    k_zero<<<1, 128>>>(out);

    for (int layer = 0; layer < NLAYERS; layer++) {
        // Ml[row][l*128+o] = h[row,:] @ A[l]  (tf32x3 == fp32-accurate)
        k_gemm3<1><<<dim3(64, 5), 256, GEMM_SMEM>>>(
            p_h, nullptr, nullptr, nullptr, A, nullptr, p_Ml, 128, 128*128, 640);
        // exact gather aggregation, 4-way w-split partials
        k_agg<<<dim3(128, 4), 256>>>(g, e);
        // gi = (P0+P1+P2+P3) @ Wi + bi ; gh = h @ Wh + bh
        k_gemm3<4><<<dim3(64, 3), 256, GEMM_SMEM>>>(
            p_P0, p_P1, p_P2, p_P3, Wi, bi, p_gi, 384, 128, 384);
        k_gemm3<1><<<dim3(64, 3), 256, GEMM_SMEM>>>(
            p_h, nullptr, nullptr, nullptr, Wh, bh, p_gh, 384, 128, 384);
        k_gru<<<ROWS*HH/256, 256>>>();
    }

    k_readout<<<ROWS, 128>>>(Wg, bg, Wo, bo, out);
}

// round 5
// speedup vs baseline: 1.1960x; 1.0398x over previous
#include <cuda_runtime.h>
#include <cstdint>

#define BB 8
#define NN 1024
#define DIN 64
#define HH 128
#define MSGD 128
#define LL 5
#define TGT 12
#define NLAYERS 3
#define ROWS (BB*NN)   // 8192

// ================= scratch =================
__device__ float g_h   [ROWS*HH];
__device__ float g_h0  [ROWS*HH];
__device__ float g_hh  [ROWS*HH];        // tf32-hi plane of h
__device__ float g_hl  [ROWS*HH];        // tf32-lo plane of h
__device__ float g_Ml  [ROWS*LL*MSGD];   // [row][l*128+o], exact fp32
__device__ float g_aggP[4][ROWS*MSGD];   // 4-way w-split partials
__device__ float g_msh [ROWS*MSGD];      // split aggsum hi
__device__ float g_msl [ROWS*MSGD];      // split aggsum lo
__device__ float g_gi  [ROWS*3*HH];
__device__ float g_gh  [ROWS*3*HH];
__device__ float g_Ah  [LL*HH*MSGD];     // split weights
__device__ float g_Al  [LL*HH*MSGD];
__device__ float g_Wih [HH*3*HH];
__device__ float g_Wil [HH*3*HH];
__device__ float g_Whh [HH*3*HH];
__device__ float g_Whl [HH*3*HH];
__device__ float g_maskN[ROWS];
__device__ float g_maskR[ROWS];

// ================= helpers =================
__device__ __forceinline__ uint32_t smem_u32(const void* p){
    uint32_t a;
    asm("{ .reg .u64 t; cvta.to.shared.u64 t, %1; cvt.u32.u64 %0, t; }" : "=r"(a) : "l"(p));
    return a;
}
__device__ __forceinline__ uint32_t f2tf(float f){
    uint32_t u; asm("cvt.rna.tf32.f32 %0, %1;" : "=r"(u) : "f"(f)); return u;
}
__device__ __forceinline__ void mma_tf32(float* d, const uint32_t* a, const uint32_t* b){
    asm volatile("mma.sync.aligned.m16n8k8.row.col.f32.tf32.tf32.f32 "
        "{%0,%1,%2,%3}, {%4,%5,%6,%7}, {%8,%9}, {%0,%1,%2,%3};"
        : "+f"(d[0]), "+f"(d[1]), "+f"(d[2]), "+f"(d[3])
        : "r"(a[0]), "r"(a[1]), "r"(a[2]), "r"(a[3]), "r"(b[0]), "r"(b[1]));
}
#define CP_ASYNC16(dst, src) \
    asm volatile("cp.async.cg.shared.global [%0], [%1], 16;" :: "r"(dst), "l"(src))
#define CP_COMMIT() asm volatile("cp.async.commit_group;")
#define CP_WAIT(n)  asm volatile("cp.async.wait_group %0;" :: "n"(n))

// ================= init / split =================
__global__ void k_init(const float* __restrict__ h_in)
{
    int n = blockIdx.x;
    int t = threadIdx.x;
    float v = (t < DIN) ? h_in[n*DIN + t] : 0.f;
    g_h0[n*HH + t] = v;
    g_h [n*HH + t] = v;
    float hi = __uint_as_float(f2tf(v));
    g_hh[n*HH + t] = hi;
    g_hl[n*HH + t] = __uint_as_float(f2tf(v - hi));
    __shared__ float sa[128], ss[128];
    sa[t] = fabsf(v); ss[t] = v;
    __syncthreads();
    for (int s = 64; s > 0; s >>= 1) {
        if (t < s) { sa[t] += sa[t+s]; ss[t] += ss[t+s]; }
        __syncthreads();
    }
    if (t == 0) {
        g_maskN[n] = (sa[0] > 0.f) ? 1.f : 0.f;
        g_maskR[n] = (ss[0] > 0.f) ? 1.f : 0.f;
    }
}

__global__ void k_zero(float* __restrict__ out)
{
    int i = threadIdx.x;
    if (i < BB*TGT) out[i] = 0.f;
}

__global__ void k_split(const float* __restrict__ src,
                        float* __restrict__ dh, float* __restrict__ dl, int n)
{
    int i = blockIdx.x*256 + threadIdx.x;
    if (i < n) {
        float v = src[i];
        float hi = __uint_as_float(f2tf(v));
        dh[i] = hi;
        dl[i] = __uint_as_float(f2tf(v - hi));
    }
}

// sum 4 agg partials -> split planes
__global__ void k_aggsum()
{
    int i = blockIdx.x*256 + threadIdx.x;   // ROWS*128/4 float4
    const float4* p0 = (const float4*)g_aggP[0];
    const float4* p1 = (const float4*)g_aggP[1];
    const float4* p2 = (const float4*)g_aggP[2];
    const float4* p3 = (const float4*)g_aggP[3];
    float4 a = p0[i], b = p1[i], c = p2[i], d = p3[i];
    float4 s;
    s.x = (a.x+b.x)+(c.x+d.x); s.y = (a.y+b.y)+(c.y+d.y);
    s.z = (a.z+b.z)+(c.z+d.z); s.w = (a.w+b.w)+(c.w+d.w);
    float4 h4, l4;
    h4.x = __uint_as_float(f2tf(s.x)); l4.x = __uint_as_float(f2tf(s.x - h4.x));
    h4.y = __uint_as_float(f2tf(s.y)); l4.y = __uint_as_float(f2tf(s.y - h4.y));
    h4.z = __uint_as_float(f2tf(s.z)); l4.z = __uint_as_float(f2tf(s.z - h4.z));
    h4.w = __uint_as_float(f2tf(s.w)); l4.w = __uint_as_float(f2tf(s.w - h4.w));
    ((float4*)g_msh)[i] = h4;
    ((float4*)g_msl)[i] = l4;
}

// ================= gemm core (pre-split operands, cp.async pipeline) =================
// C[row0+128, cBase+128] = X @ W + bias. K=128, chunks of 16, double-buffered.
// 256 thr = 8 warps, warp = 32v x 64o. Pitches: X 20, W 136.
#define GEMM_SMEM ((4*2560 + 4*2176)*4)   // 75776 B

__device__ __forceinline__ void gemm_core(
    const float* __restrict__ Xh, const float* __restrict__ Xl,
    const float* __restrict__ Wph, const float* __restrict__ Wpl,
    const float* __restrict__ bias, float* __restrict__ C,
    int ldW, int ldC, int cBase, int row0, float* smf)
{
    float* sXh = smf;                    // [2][2560]
    float* sXl = smf + 5120;
    float* sWh = smf + 10240;            // [2][2176]
    float* sWl = smf + 10240 + 4352;
    const uint32_t uXh = smem_u32(sXh), uXl = smem_u32(sXl);
    const uint32_t uWh = smem_u32(sWh), uWl = smem_u32(sWl);

    const int tid = threadIdx.x, lane = tid & 31, wid = tid >> 5;
    const int tq = lane & 3, gid = lane >> 2;
    const int vbase = (wid >> 1) << 5;
    const int obase = (wid & 1) << 6;

    float acc[2][8][4];
#pragma unroll
    for (int i = 0; i < 2; i++)
#pragma unroll
        for (int j = 0; j < 8; j++)
#pragma unroll
            for (int k = 0; k < 4; k++) acc[i][j][k] = 0.f;

    auto stage = [&](int c) {
        int buf = c & 1; int k0 = c << 4;
#pragma unroll
        for (int r = 0; r < 2; r++) {
            int idx = (r << 8) + tid; int v = idx >> 2, k4 = idx & 3;
            size_t off = (size_t)(row0 + v)*HH + k0 + (k4 << 2);
            uint32_t d = (uint32_t)(buf*2560 + v*20 + (k4 << 2))*4;
            CP_ASYNC16(uXh + d, Xh + off);
            CP_ASYNC16(uXl + d, Xl + off);
        }
#pragma unroll
        for (int r = 0; r < 2; r++) {
            int idx = (r << 8) + tid; int k = idx >> 5, o4 = idx & 31;
            size_t off = (size_t)(k0 + k)*ldW + (o4 << 2);
            uint32_t d = (uint32_t)(buf*2176 + k*136 + (o4 << 2))*4;
            CP_ASYNC16(uWh + d, Wph + off);
            CP_ASYNC16(uWl + d, Wpl + off);
        }
        CP_COMMIT();
    };

    stage(0);
    for (int c = 0; c < 8; c++) {
        int buf = c & 1;
        if (c < 7) { stage(c + 1); CP_WAIT(1); }
        else       { CP_WAIT(0); }
        __syncthreads();
        const uint32_t* bXh = (const uint32_t*)(sXh + buf*2560);
        const uint32_t* bXl = (const uint32_t*)(sXl + buf*2560);
        const uint32_t* bWh = (const uint32_t*)(sWh + buf*2176);
        const uint32_t* bWl = (const uint32_t*)(sWl + buf*2176);
#pragma unroll
        for (int k8 = 0; k8 < 2; k8++) {
            int kk = (k8 << 3) + tq;
            uint32_t ah[2][4], al[2][4];
#pragma unroll
            for (int mt = 0; mt < 2; mt++) {
                int vr = vbase + (mt << 4) + gid;
                ah[mt][0] = bXh[vr*20 + kk];       ah[mt][1] = bXh[(vr+8)*20 + kk];
                ah[mt][2] = bXh[vr*20 + kk + 4];   ah[mt][3] = bXh[(vr+8)*20 + kk + 4];
                al[mt][0] = bXl[vr*20 + kk];       al[mt][1] = bXl[(vr+8)*20 + kk];
                al[mt][2] = bXl[vr*20 + kk + 4];   al[mt][3] = bXl[(vr+8)*20 + kk + 4];
            }
#pragma unroll
            for (int nt = 0; nt < 8; nt++) {
                int o = obase + (nt << 3) + gid;
                uint32_t bh2[2] = { bWh[kk*136 + o], bWh[(kk+4)*136 + o] };
                uint32_t bl2[2] = { bWl[kk*136 + o], bWl[(kk+4)*136 + o] };
                mma_tf32(acc[0][nt], ah[0], bh2);
                mma_tf32(acc[0][nt], ah[0], bl2);
                mma_tf32(acc[0][nt], al[0], bh2);
                mma_tf32(acc[1][nt], ah[1], bh2);
                mma_tf32(acc[1][nt], ah[1], bl2);
                mma_tf32(acc[1][nt], al[1], bh2);
            }
        }
        __syncthreads();
    }

#pragma unroll
    for (int mt = 0; mt < 2; mt++)
#pragma unroll
        for (int nt = 0; nt < 8; nt++) {
            int row = row0 + vbase + (mt << 4) + gid;
            int col = cBase + obase + (nt << 3) + (tq << 1);
            float b0 = 0.f, b1 = 0.f;
            if (bias) { b0 = bias[col - cBase]; b1 = bias[col - cBase + 1]; }
            *(float2*)&C[(size_t)row*ldC + col] =
                make_float2(acc[mt][nt][0] + b0, acc[mt][nt][1] + b1);
            *(float2*)&C[(size_t)(row + 8)*ldC + col] =
                make_float2(acc[mt][nt][2] + b0, acc[mt][nt][3] + b1);
        }
}

// merged Ml-gemm (y 0..4) + Wh-gemm (y 5..7); X = split h
__global__ void __launch_bounds__(256, 2) k_gemmA(const float* __restrict__ bh)
{
    extern __shared__ float smf[];
    int y = blockIdx.y;
    int row0 = blockIdx.x << 7;
    if (y < 5) {
        gemm_core(g_hh, g_hl, g_Ah + y*HH*MSGD, g_Al + y*HH*MSGD,
                  nullptr, g_Ml, 128, 640, y << 7, row0, smf);
    } else {
        int yy = y - 5;
        gemm_core(g_hh, g_hl, g_Whh + (yy << 7), g_Whl + (yy << 7),
                  bh + (yy << 7), g_gh, 384, 384, yy << 7, row0, smf);
    }
}

// Wi gemm: X = split aggsum
__global__ void __launch_bounds__(256, 2) k_gemmWi(const float* __restrict__ bi)
{
    extern __shared__ float smf[];
    int y = blockIdx.y;
    int row0 = blockIdx.x << 7;
    gemm_core(g_msh, g_msl, g_Wih + (y << 7), g_Wil + (y << 7),
              bi + (y << 7), g_gi, 384, 384, y << 7, row0, smf);
}

// ================= exact fp32 gather aggregation (unchanged from R4) =================
__global__ void __launch_bounds__(256, 4) k_agg(
    const float* __restrict__ g, const int* __restrict__ e)
{
    __shared__ float4 sM[8][LL][32];
    __shared__ float2 sGE[64][8];

    const int tid = threadIdx.x, lane = tid & 31, wid = tid >> 5;
    const int b  = blockIdx.x >> 4;
    const int v0 = (blockIdx.x & 15) << 6;
    const int wbeg = blockIdx.y << 8;

    float4 acc[8];
#pragma unroll
    for (int i = 0; i < 8; i++) acc[i] = make_float4(0.f, 0.f, 0.f, 0.f);

    for (int c = 0; c < 32; c++) {
        int w0 = wbeg + (c << 3);
        {
            const float4* src = (const float4*)(g_Ml + (size_t)((b << 10) + w0)*640);
            float4* dstM = &sM[0][0][0];
#pragma unroll
            for (int r = 0; r < 5; r++) dstM[r*256 + tid] = src[r*256 + tid];
        }
        {
            int v = tid >> 2, wp = tid & 3;
            size_t off = ((size_t)((b << 10) + v0 + v) << 10) + w0 + (wp << 1);
            float2 gg = *(const float2*)(g + off);
            int2   ee = *(const int2*)(e + off);
            sGE[v][(wp << 1)    ] = make_float2(gg.x, __int_as_float(ee.x));
            sGE[v][(wp << 1) + 1] = make_float2(gg.y, __int_as_float(ee.y));
        }
        __syncthreads();
#pragma unroll
        for (int i = 0; i < 8; i++) {
            int v = (wid << 3) + i;
#pragma unroll
            for (int w = 0; w < 8; w++) {
                float2 ge = sGE[v][w];
                int lab = __float_as_int(ge.y);
                float4 m = sM[w][lab][lane];
                acc[i].x += ge.x * m.x; acc[i].y += ge.x * m.y;
                acc[i].z += ge.x * m.z; acc[i].w += ge.x * m.w;
            }
        }
        __syncthreads();
    }

    float* dst = g_aggP[blockIdx.y];
#pragma unroll
    for (int i = 0; i < 8; i++) {
        int row = (b << 10) + v0 + (wid << 3) + i;
        *(float4*)&dst[(size_t)row*128 + (lane << 2)] = acc[i];
    }
}

// ================= GRU (writes h + split planes) =================
__global__ void k_gru()
{
    int idx = blockIdx.x*256 + threadIdx.x;
    int n = idx >> 7;
    int c = idx & 127;
    int base = n*384 + c;
    float ir = g_gi[base], iz = g_gi[base+128], in_ = g_gi[base+256];
    float hr = g_gh[base], hz = g_gh[base+128], hn  = g_gh[base+256];
    float r = 1.f/(1.f + __expf(-(ir + hr)));
    float z = 1.f/(1.f + __expf(-(iz + hz)));
    float nn = tanhf(in_ + r*hn);
    float h  = g_h[idx];
    float v = ((1.f - z)*nn + z*h) * g_maskN[n];
    g_h[idx] = v;
    float hi = __uint_as_float(f2tf(v));
    g_hh[idx] = hi;
    g_hl[idx] = __uint_as_float(f2tf(v - hi));
}

// ================= readout =================
__global__ void k_readout(const float* __restrict__ Wg, const float* __restrict__ bg,
                          const float* __restrict__ Wo, const float* __restrict__ bo,
                          float* __restrict__ out)
{
    int n = blockIdx.x;
    int t = threadIdx.x;
    float hT = g_h [n*HH + t];
    float h0 = g_h0[n*HH + t];
    __shared__ float red[24][128];
    __shared__ float s2[24];
#pragma unroll
    for (int j = 0; j < TGT; j++) {
        red[j][t]      = hT*Wg[t*TGT + j] + h0*Wg[(HH + t)*TGT + j];
        red[12 + j][t] = hT*Wo[t*TGT + j];
    }
    __syncthreads();
    if (t < 24) {
        float s = 0.f;
        for (int i = 0; i < 128; i++) s += red[t][i];
        s2[t] = s;
    }
    __syncthreads();
    if (t < TGT) {
        float gate = 1.f/(1.f + __expf(-(s2[t] + bg[t])));
        float val  = gate*(s2[12 + t] + bo[t]) * g_maskR[n];
        atomicAdd(&out[(n >> 10)*TGT + t], val);
    }
}

// ================= launch =================
extern "C" void kernel_launch(void* const* d_in, const int* in_sizes, int n_in,
                              void* d_out, int out_size)
{
    const float* g    = (const float*)d_in[0];
    const float* h_in = (const float*)d_in[1];
    const int*   e    = (const int*)  d_in[2];
    const float* A    = (const float*)d_in[3];
    const float* Wi   = (const float*)d_in[4];
    const float* Wh   = (const float*)d_in[5];
    const float* bi   = (const float*)d_in[6];
    const float* bh   = (const float*)d_in[7];
    const float* Wg   = (const float*)d_in[8];
    const float* bg   = (const float*)d_in[9];
    const float* Wo   = (const float*)d_in[10];
    const float* bo   = (const float*)d_in[11];
    float* out = (float*)d_out;

    static int attr_set = 0;
    if (!attr_set) {
        cudaFuncSetAttribute(k_gemmA,  cudaFuncAttributeMaxDynamicSharedMemorySize, GEMM_SMEM);
        cudaFuncSetAttribute(k_gemmWi, cudaFuncAttributeMaxDynamicSharedMemorySize, GEMM_SMEM);
        attr_set = 1;
    }

    float *p_Ah, *p_Al, *p_Wih, *p_Wil, *p_Whh, *p_Whl;
    cudaGetSymbolAddress((void**)&p_Ah,  g_Ah);
    cudaGetSymbolAddress((void**)&p_Al,  g_Al);
    cudaGetSymbolAddress((void**)&p_Wih, g_Wih);
    cudaGetSymbolAddress((void**)&p_Wil, g_Wil);
    cudaGetSymbolAddress((void**)&p_Whh, g_Whh);
    cudaGetSymbolAddress((void**)&p_Whl, g_Whl);

    k_init<<<ROWS, 128>>>(h_in);
    k_zero<<<1, 128>>>(out);
    k_split<<<(LL*HH*MSGD + 255)/256, 256>>>(A,  p_Ah,  p_Al,  LL*HH*MSGD);
    k_split<<<(HH*3*HH + 255)/256, 256>>>(Wi, p_Wih, p_Wil, HH*3*HH);
    k_split<<<(HH*3*HH + 255)/256, 256>>>(Wh, p_Whh, p_Whl, HH*3*HH);

    for (int layer = 0; layer < NLAYERS; layer++) {
        // Ml (y 0..4) + gh (y 5..7) in one launch
        k_gemmA<<<dim3(64, 8), 256, GEMM_SMEM>>>(bh);
        // exact gather aggregation, 4-way w-split partials
        k_agg<<<dim3(128, 4), 256>>>(g, e);
        // sum partials + tf32-split
        k_aggsum<<<ROWS*MSGD/4/256, 256>>>();
        // gi = aggsum @ Wi + bi
        k_gemmWi<<<dim3(64, 3), 256, GEMM_SMEM>>>(bi);
        k_gru<<<ROWS*HH/256, 256>>>();
    }

    k_readout<<<ROWS, 128>>>(Wg, bg, Wo, bo, out);
}

// round 6
// speedup vs baseline: 1.4465x; 1.2095x over previous
#include <cuda_runtime.h>
#include <cstdint>

#define BB 8
#define NN 1024
#define DIN 64
#define HH 128
#define MSGD 128
#define LL 5
#define TGT 12
#define NLAYERS 3
#define ROWS (BB*NN)   // 8192

// ================= scratch =================
__device__ float    g_h   [ROWS*HH];
__device__ float    g_h0  [ROWS*HH];
__device__ uint32_t g_hh  [ROWS*64];       // bf16x2 hi plane of h (k-pairs)
__device__ uint32_t g_hl  [ROWS*64];       // bf16x2 lo plane
__device__ float    g_Ml  [ROWS*LL*MSGD];  // exact fp32 messages
__device__ float    g_aggP[4][ROWS*MSGD];  // w-split partials
__device__ uint32_t g_msh [ROWS*64];       // bf16x2 split of aggsum
__device__ uint32_t g_msl [ROWS*64];
__device__ float    g_gi  [ROWS*3*HH];
__device__ float    g_gh  [ROWS*3*HH];
__device__ uint32_t g_Ahp [320*128];       // packed split weights [k2][o]
__device__ uint32_t g_Alp [320*128];
__device__ uint32_t g_Wihp[64*384];
__device__ uint32_t g_Wilp[64*384];
__device__ uint32_t g_Whhp[64*384];
__device__ uint32_t g_Whlp[64*384];
__device__ float    g_maskN[ROWS];
__device__ float    g_maskR[ROWS];

// ================= helpers =================
__device__ __forceinline__ uint32_t smem_u32(const void* p){
    uint32_t a;
    asm("{ .reg .u64 t; cvta.to.shared.u64 t, %1; cvt.u32.u64 %0, t; }" : "=r"(a) : "l"(p));
    return a;
}
// pack: lower 16 bits = x0 (even k), upper = x1 (odd k)
__device__ __forceinline__ uint32_t packbf(float x0, float x1){
    uint32_t r; asm("cvt.rn.bf16x2.f32 %0, %1, %2;" : "=r"(r) : "f"(x1), "f"(x0)); return r;
}
__device__ __forceinline__ float bflo(uint32_t p){ return __uint_as_float(p << 16); }
__device__ __forceinline__ float bfhi(uint32_t p){ return __uint_as_float(p & 0xFFFF0000u); }

__device__ __forceinline__ void mma_bf16(float* d, const uint32_t* a, const uint32_t* b){
    asm volatile("mma.sync.aligned.m16n8k16.row.col.f32.bf16.bf16.f32 "
        "{%0,%1,%2,%3}, {%4,%5,%6,%7}, {%8,%9}, {%0,%1,%2,%3};"
        : "+f"(d[0]), "+f"(d[1]), "+f"(d[2]), "+f"(d[3])
        : "r"(a[0]), "r"(a[1]), "r"(a[2]), "r"(a[3]), "r"(b[0]), "r"(b[1]));
}
#define CP_ASYNC16(dst, src) \
    asm volatile("cp.async.cg.shared.global [%0], [%1], 16;" :: "r"(dst), "l"(src))
#define CP_COMMIT() asm volatile("cp.async.commit_group;")
#define CP_WAIT0()  asm volatile("cp.async.wait_group 0;")

// ================= init =================
__global__ void k_init(const float* __restrict__ h_in)
{
    int n = blockIdx.x;
    int t = threadIdx.x;    // 128
    float v = (t < DIN) ? h_in[n*DIN + t] : 0.f;
    g_h0[n*HH + t] = v;
    g_h [n*HH + t] = v;
    __shared__ float sv[128], sa[128], ss[128];
    sv[t] = v; sa[t] = fabsf(v); ss[t] = v;
    __syncthreads();
    for (int s = 64; s > 0; s >>= 1) {
        if (t < s) { sa[t] += sa[t+s]; ss[t] += ss[t+s]; }
        __syncthreads();
    }
    if (t < 64) {
        float x0 = sv[2*t], x1 = sv[2*t + 1];
        uint32_t hi = packbf(x0, x1);
        g_hh[n*64 + t] = hi;
        g_hl[n*64 + t] = packbf(x0 - bflo(hi), x1 - bfhi(hi));
    }
    if (t == 0) {
        g_maskN[n] = (sa[0] > 0.f) ? 1.f : 0.f;
        g_maskR[n] = (ss[0] > 0.f) ? 1.f : 0.f;
    }
}

__global__ void k_zero(float* __restrict__ out)
{
    int i = threadIdx.x;
    if (i < BB*TGT) out[i] = 0.f;
}

// split weights: W [2*nK2][nO] fp32 -> packed bf16x2 hi/lo planes [nK2][nO]
__global__ void k_splitW(const float* __restrict__ W,
                         uint32_t* __restrict__ dh, uint32_t* __restrict__ dl,
                         int nK2, int nO)
{
    int i = blockIdx.x*256 + threadIdx.x;
    if (i < nK2*nO) {
        int k2 = i / nO, o = i - k2*nO;
        float w0 = W[(2*k2)*nO + o];
        float w1 = W[(2*k2 + 1)*nO + o];
        uint32_t hi = packbf(w0, w1);
        dh[i] = hi;
        dl[i] = packbf(w0 - bflo(hi), w1 - bfhi(hi));
    }
}

// sum 4 agg partials -> packed split planes
__global__ void k_aggsum()
{
    int i = blockIdx.x*256 + threadIdx.x;   // ROWS*32 float4s
    const float4* p0 = (const float4*)g_aggP[0];
    const float4* p1 = (const float4*)g_aggP[1];
    const float4* p2 = (const float4*)g_aggP[2];
    const float4* p3 = (const float4*)g_aggP[3];
    float4 a = p0[i], b = p1[i], c = p2[i], d = p3[i];
    float4 s;
    s.x = (a.x+b.x)+(c.x+d.x); s.y = (a.y+b.y)+(c.y+d.y);
    s.z = (a.z+b.z)+(c.z+d.z); s.w = (a.w+b.w)+(c.w+d.w);
    uint32_t h0 = packbf(s.x, s.y), h1 = packbf(s.z, s.w);
    uint32_t l0 = packbf(s.x - bflo(h0), s.y - bfhi(h0));
    uint32_t l1 = packbf(s.z - bflo(h1), s.w - bfhi(h1));
    ((uint2*)g_msh)[i] = make_uint2(h0, h1);
    ((uint2*)g_msl)[i] = make_uint2(l0, l1);
}

// ================= bf16x3 gemm core =================
// C[row0+128, cBase+128] = X @ W + bias (fp32-accurate via 3-term bf16 split).
// X planes: packed uint32 [row][64]. W planes: packed [64][ldW].
// K=128 -> 4 chunks of 32 (16 k2), cp.async double-buffered.
// 256 thr = 8 warps, warp = 32v x 64o.
#define GEMM_SMEM ((2*2560 + 2*2560 + 2*2176 + 2*2176)*4)   // 75776 B

__device__ __forceinline__ void gemm_core(
    const uint32_t* __restrict__ Xh, const uint32_t* __restrict__ Xl,
    const uint32_t* __restrict__ Wph, const uint32_t* __restrict__ Wpl,
    const float* __restrict__ bias, float* __restrict__ C,
    int ldW, int ldC, int cBase, int row0, uint32_t* smu)
{
    uint32_t* sXh = smu;                 // [2][2560]  pitch 20
    uint32_t* sXl = smu + 5120;
    uint32_t* sWh = smu + 10240;         // [2][2176]  pitch 136
    uint32_t* sWl = smu + 14592;
    const uint32_t uXh = smem_u32(sXh), uXl = smem_u32(sXl);
    const uint32_t uWh = smem_u32(sWh), uWl = smem_u32(sWl);

    const int tid = threadIdx.x, lane = tid & 31, wid = tid >> 5;
    const int tq = lane & 3, gid = lane >> 2;
    const int vbase = (wid >> 1) << 5;
    const int obase = (wid & 1) << 6;

    float acc[2][8][4];
#pragma unroll
    for (int i = 0; i < 2; i++)
#pragma unroll
        for (int j = 0; j < 8; j++)
#pragma unroll
            for (int k = 0; k < 4; k++) acc[i][j][k] = 0.f;

    auto stage = [&](int c) {
        int buf = c & 1; int k02 = c << 4;
#pragma unroll
        for (int r = 0; r < 2; r++) {
            int idx = (r << 8) + tid; int v = idx >> 2, q = idx & 3;
            size_t off = (size_t)(row0 + v)*64 + k02 + (q << 2);
            uint32_t d = (uint32_t)(buf*2560 + v*20 + (q << 2))*4;
            CP_ASYNC16(uXh + d, Xh + off);
            CP_ASYNC16(uXl + d, Xl + off);
        }
#pragma unroll
        for (int r = 0; r < 2; r++) {
            int idx = (r << 8) + tid; int k2 = idx >> 5, o4 = idx & 31;
            size_t off = (size_t)(k02 + k2)*ldW + (o4 << 2);
            uint32_t d = (uint32_t)(buf*2176 + k2*136 + (o4 << 2))*4;
            CP_ASYNC16(uWh + d, Wph + off);
            CP_ASYNC16(uWl + d, Wpl + off);
        }
        CP_COMMIT();
    };

    stage(0);
    for (int c = 0; c < 4; c++) {
        CP_WAIT0();
        __syncthreads();
        if (c < 3) stage(c + 1);
        int buf = c & 1;
        const uint32_t* bXh = sXh + buf*2560;
        const uint32_t* bXl = sXl + buf*2560;
        const uint32_t* bWh = sWh + buf*2176;
        const uint32_t* bWl = sWl + buf*2176;
#pragma unroll
        for (int h = 0; h < 2; h++) {
            int kk2 = (h << 3) + tq;
            uint32_t ah[2][4], al[2][4];
#pragma unroll
            for (int mt = 0; mt < 2; mt++) {
                int vr = vbase + (mt << 4) + gid;
                ah[mt][0] = bXh[vr*20 + kk2];       ah[mt][1] = bXh[(vr+8)*20 + kk2];
                ah[mt][2] = bXh[vr*20 + kk2 + 4];   ah[mt][3] = bXh[(vr+8)*20 + kk2 + 4];
                al[mt][0] = bXl[vr*20 + kk2];       al[mt][1] = bXl[(vr+8)*20 + kk2];
                al[mt][2] = bXl[vr*20 + kk2 + 4];   al[mt][3] = bXl[(vr+8)*20 + kk2 + 4];
            }
#pragma unroll
            for (int nt = 0; nt < 8; nt++) {
                int o = obase + (nt << 3) + gid;
                uint32_t bh2[2] = { bWh[kk2*136 + o], bWh[(kk2+4)*136 + o] };
                uint32_t bl2[2] = { bWl[kk2*136 + o], bWl[(kk2+4)*136 + o] };
                mma_bf16(acc[0][nt], ah[0], bh2);
                mma_bf16(acc[0][nt], ah[0], bl2);
                mma_bf16(acc[0][nt], al[0], bh2);
                mma_bf16(acc[1][nt], ah[1], bh2);
                mma_bf16(acc[1][nt], ah[1], bl2);
                mma_bf16(acc[1][nt], al[1], bh2);
            }
        }
    }

#pragma unroll
    for (int mt = 0; mt < 2; mt++)
#pragma unroll
        for (int nt = 0; nt < 8; nt++) {
            int row = row0 + vbase + (mt << 4) + gid;
            int col = cBase + obase + (nt << 3) + (tq << 1);
            float b0 = 0.f, b1 = 0.f;
            if (bias) { b0 = bias[col - cBase]; b1 = bias[col - cBase + 1]; }
            *(float2*)&C[(size_t)row*ldC + col] =
                make_float2(acc[mt][nt][0] + b0, acc[mt][nt][1] + b1);
            *(float2*)&C[(size_t)(row + 8)*ldC + col] =
                make_float2(acc[mt][nt][2] + b0, acc[mt][nt][3] + b1);
        }
}

// merged Ml-gemm (y 0..4) + Wh-gemm (y 5..7)
__global__ void __launch_bounds__(256, 2) k_gemmA(const float* __restrict__ bh)
{
    extern __shared__ uint32_t smu[];
    int y = blockIdx.y;
    int row0 = blockIdx.x << 7;
    if (y < 5) {
        gemm_core(g_hh, g_hl, g_Ahp + y*64*128, g_Alp + y*64*128,
                  nullptr, g_Ml, 128, 640, y << 7, row0, smu);
    } else {
        int yy = y - 5;
        gemm_core(g_hh, g_hl, g_Whhp + (yy << 7), g_Whlp + (yy << 7),
                  bh + (yy << 7), g_gh, 384, 384, yy << 7, row0, smu);
    }
}

__global__ void __launch_bounds__(256, 2) k_gemmWi(const float* __restrict__ bi)
{
    extern __shared__ uint32_t smu[];
    int y = blockIdx.y;
    int row0 = blockIdx.x << 7;
    gemm_core(g_msh, g_msl, g_Wihp + (y << 7), g_Wilp + (y << 7),
              bi + (y << 7), g_gi, 384, 384, y << 7, row0, smu);
}

// ================= exact fp32 gather aggregation (cp.async double-buffered) =================
// Per buffer (24576 B): [0,20480) sM floats, [20480,22528) sG, [22528,24576) sE
#define AGG_SMEM (2*24576)

__global__ void __launch_bounds__(256, 4) k_agg(
    const float* __restrict__ g, const int* __restrict__ e)
{
    extern __shared__ float sm[];
    const uint32_t base_u = smem_u32(sm);

    const int tid = threadIdx.x, lane = tid & 31, wid = tid >> 5;
    const int b  = blockIdx.x >> 4;
    const int v0 = (blockIdx.x & 15) << 6;
    const int wbeg = blockIdx.y << 8;

    float4 acc[8];
#pragma unroll
    for (int i = 0; i < 8; i++) acc[i] = make_float4(0.f, 0.f, 0.f, 0.f);

    auto stage = [&](int c) {
        int w0 = wbeg + (c << 3);
        int buf = c & 1;
        const float* src = g_Ml + (size_t)((b << 10) + w0)*640;
#pragma unroll
        for (int r = 0; r < 5; r++)
            CP_ASYNC16(base_u + buf*24576 + (((r << 8) + tid) << 4),
                       src + (((r << 8) + tid) << 2));
        if (tid < 128) {
            int v = tid >> 1, hf = tid & 1;
            CP_ASYNC16(base_u + buf*24576 + 20480 + ((v << 3) + (hf << 2))*4,
                       g + ((size_t)((b << 10) + v0 + v) << 10) + w0 + (hf << 2));
        } else {
            int t2 = tid - 128; int v = t2 >> 1, hf = t2 & 1;
            CP_ASYNC16(base_u + buf*24576 + 22528 + ((v << 3) + (hf << 2))*4,
                       e + ((size_t)((b << 10) + v0 + v) << 10) + w0 + (hf << 2));
        }
        CP_COMMIT();
    };

    stage(0);
    for (int c = 0; c < 32; c++) {
        CP_WAIT0();
        __syncthreads();
        if (c < 31) stage(c + 1);
        int buf = c & 1;
        const float4* sM4 = (const float4*)(sm + buf*6144);
        const float*  sG  = sm + buf*6144 + 5120;
        const int*    sE  = (const int*)sm + buf*6144 + 5632;
#pragma unroll
        for (int i = 0; i < 8; i++) {
            int v = (wid << 3) + i;
#pragma unroll
            for (int w = 0; w < 8; w++) {
                float gv  = sG[(v << 3) + w];
                int   lab = sE[(v << 3) + w];
                float4 m = sM4[w*160 + lab*32 + lane];
                acc[i].x += gv*m.x; acc[i].y += gv*m.y;
                acc[i].z += gv*m.z; acc[i].w += gv*m.w;
            }
        }
    }

    float* dst = g_aggP[blockIdx.y];
#pragma unroll
    for (int i = 0; i < 8; i++) {
        int row = (b << 10) + v0 + (wid << 3) + i;
        *(float4*)&dst[(size_t)row*128 + (lane << 2)] = acc[i];
    }
}

// ================= GRU (pairs; writes h + packed planes) =================
__global__ void k_gru()
{
    int idx = blockIdx.x*256 + threadIdx.x;   // ROWS*64
    int n = idx >> 6;
    int c2 = idx & 63;
    int base = n*384 + (c2 << 1);
    float2 ir = *(float2*)&g_gi[base];
    float2 iz = *(float2*)&g_gi[base + 128];
    float2 in_ = *(float2*)&g_gi[base + 256];
    float2 hr = *(float2*)&g_gh[base];
    float2 hz = *(float2*)&g_gh[base + 128];
    float2 hn = *(float2*)&g_gh[base + 256];
    float2 h2 = *(float2*)&g_h[(n << 7) + (c2 << 1)];
    float mask = g_maskN[n];

    float r0 = 1.f/(1.f + __expf(-(ir.x + hr.x)));
    float z0 = 1.f/(1.f + __expf(-(iz.x + hz.x)));
    float n0 = tanhf(in_.x + r0*hn.x);
    float v0 = ((1.f - z0)*n0 + z0*h2.x) * mask;
    float r1 = 1.f/(1.f + __expf(-(ir.y + hr.y)));
    float z1 = 1.f/(1.f + __expf(-(iz.y + hz.y)));
    float n1 = tanhf(in_.y + r1*hn.y);
    float v1 = ((1.f - z1)*n1 + z1*h2.y) * mask;

    *(float2*)&g_h[(n << 7) + (c2 << 1)] = make_float2(v0, v1);
    uint32_t hi = packbf(v0, v1);
    g_hh[idx] = hi;
    g_hl[idx] = packbf(v0 - bflo(hi), v1 - bfhi(hi));
}

// ================= readout =================
__global__ void k_readout(const float* __restrict__ Wg, const float* __restrict__ bg,
                          const float* __restrict__ Wo, const float* __restrict__ bo,
                          float* __restrict__ out)
{
    int n = blockIdx.x;
    int t = threadIdx.x;
    float hT = g_h [n*HH + t];
    float h0 = g_h0[n*HH + t];
    __shared__ float red[24][128];
    __shared__ float s2[24];
#pragma unroll
    for (int j = 0; j < TGT; j++) {
        red[j][t]      = hT*Wg[t*TGT + j] + h0*Wg[(HH + t)*TGT + j];
        red[12 + j][t] = hT*Wo[t*TGT + j];
    }
    __syncthreads();
    if (t < 24) {
        float s = 0.f;
        for (int i = 0; i < 128; i++) s += red[t][i];
        s2[t] = s;
    }
    __syncthreads();
    if (t < TGT) {
        float gate = 1.f/(1.f + __expf(-(s2[t] + bg[t])));
        float val  = gate*(s2[12 + t] + bo[t]) * g_maskR[n];
        atomicAdd(&out[(n >> 10)*TGT + t], val);
    }
}

// ================= launch =================
extern "C" void kernel_launch(void* const* d_in, const int* in_sizes, int n_in,
                              void* d_out, int out_size)
{
    const float* g    = (const float*)d_in[0];
    const float* h_in = (const float*)d_in[1];
    const int*   e    = (const int*)  d_in[2];
    const float* A    = (const float*)d_in[3];
    const float* Wi   = (const float*)d_in[4];
    const float* Wh   = (const float*)d_in[5];
    const float* bi   = (const float*)d_in[6];
    const float* bh   = (const float*)d_in[7];
    const float* Wg   = (const float*)d_in[8];
    const float* bg   = (const float*)d_in[9];
    const float* Wo   = (const float*)d_in[10];
    const float* bo   = (const float*)d_in[11];
    float* out = (float*)d_out;

    static int attr_set = 0;
    if (!attr_set) {
        cudaFuncSetAttribute(k_gemmA,  cudaFuncAttributeMaxDynamicSharedMemorySize, GEMM_SMEM);
        cudaFuncSetAttribute(k_gemmWi, cudaFuncAttributeMaxDynamicSharedMemorySize, GEMM_SMEM);
        cudaFuncSetAttribute(k_agg,    cudaFuncAttributeMaxDynamicSharedMemorySize, AGG_SMEM);
        attr_set = 1;
    }

    uint32_t *p_Ahp, *p_Alp, *p_Wihp, *p_Wilp, *p_Whhp, *p_Whlp;
    cudaGetSymbolAddress((void**)&p_Ahp,  g_Ahp);
    cudaGetSymbolAddress((void**)&p_Alp,  g_Alp);
    cudaGetSymbolAddress((void**)&p_Wihp, g_Wihp);
    cudaGetSymbolAddress((void**)&p_Wilp, g_Wilp);
    cudaGetSymbolAddress((void**)&p_Whhp, g_Whhp);
    cudaGetSymbolAddress((void**)&p_Whlp, g_Whlp);

    k_init<<<ROWS, 128>>>(h_in);
    k_zero<<<1, 128>>>(out);
    k_splitW<<<(320*128 + 255)/256, 256>>>(A,  p_Ahp,  p_Alp,  320, 128);
    k_splitW<<<(64*384 + 255)/256, 256>>>(Wi, p_Wihp, p_Wilp, 64, 384);
    k_splitW<<<(64*384 + 255)/256, 256>>>(Wh, p_Whhp, p_Whlp, 64, 384);

    for (int layer = 0; layer < NLAYERS; layer++) {
        k_gemmA<<<dim3(64, 8), 256, GEMM_SMEM>>>(bh);
        k_agg<<<dim3(128, 4), 256, AGG_SMEM>>>(g, e);
        k_aggsum<<<ROWS*32/256, 256>>>();
        k_gemmWi<<<dim3(64, 3), 256, GEMM_SMEM>>>(bi);
        k_gru<<<ROWS*64/256, 256>>>();
    }

    k_readout<<<ROWS, 128>>>(Wg, bg, Wo, bo, out);
}